// round 1
// baseline (speedup 1.0000x reference)
#include <cuda_runtime.h>
#include <stdint.h>

#define N_NODES 65536
#define N_GRAPHS 32
#define NPG 2048
#define N_EDGES 1048576
#define F_IN 16
#define H1 64
#define H2 64
#define OUT_F 12

// ---------------- scratch (device globals: allocation-free) ----------------
__device__ float g_deg[N_NODES];
__device__ float g_dinv[N_NODES];
__device__ float g_hs1[N_NODES * H1];   // dinv-prescaled layer-1 features
__device__ float g_agg1[N_NODES * H1];  // layer-1 aggregation (init = self loop)
__device__ float g_hs2[N_NODES * H2];
__device__ float g_agg2[N_NODES * H2];

__device__ __forceinline__ float tanhx(float x) {
    float y;
    asm("tanh.approx.f32 %0, %1;" : "=f"(y) : "f"(x));
    return y;
}

__device__ __forceinline__ void red_add_v4(float* p, float4 v) {
    asm volatile("red.global.add.v4.f32 [%0], {%1,%2,%3,%4};"
                 :: "l"(p), "f"(v.x), "f"(v.y), "f"(v.z), "f"(v.w)
                 : "memory");
}

// ---------------- degree ----------------
__global__ void k_deg_init() {
    int i = blockIdx.x * blockDim.x + threadIdx.x;
    g_deg[i] = 1.0f;  // self-loop
}

__global__ void k_deg(const int* __restrict__ dst) {
    int e = blockIdx.x * blockDim.x + threadIdx.x;
    atomicAdd(&g_deg[__ldg(&dst[e])], 1.0f);
}

// ---------------- layer 1 node GEMM: hs1 = dinv * (x @ W1); agg1 init ------
__global__ void __launch_bounds__(256) k_h1(const float* __restrict__ x,
                                            const float* __restrict__ W1) {
    __shared__ float sW[F_IN * H1];
    for (int i = threadIdx.x; i < F_IN * H1; i += blockDim.x) sW[i] = W1[i];
    __syncthreads();

    int node = blockIdx.x * blockDim.x + threadIdx.x;
    float dinv = rsqrtf(g_deg[node]);
    g_dinv[node] = dinv;

    float xi[F_IN];
    const float4* x4 = reinterpret_cast<const float4*>(x + node * F_IN);
#pragma unroll
    for (int k = 0; k < F_IN / 4; k++) {
        float4 v = __ldg(&x4[k]);
        xi[4 * k + 0] = v.x; xi[4 * k + 1] = v.y;
        xi[4 * k + 2] = v.z; xi[4 * k + 3] = v.w;
    }

#pragma unroll
    for (int j = 0; j < H1; j += 4) {
        float4 a = make_float4(0.f, 0.f, 0.f, 0.f);
#pragma unroll
        for (int k = 0; k < F_IN; k++) {
            float xv = xi[k];
            a.x = fmaf(xv, sW[k * H1 + j + 0], a.x);
            a.y = fmaf(xv, sW[k * H1 + j + 1], a.y);
            a.z = fmaf(xv, sW[k * H1 + j + 2], a.z);
            a.w = fmaf(xv, sW[k * H1 + j + 3], a.w);
        }
        a.x *= dinv; a.y *= dinv; a.z *= dinv; a.w *= dinv;
        int idx = node * (H1 / 4) + (j >> 2);
        reinterpret_cast<float4*>(g_hs1)[idx] = a;
        reinterpret_cast<float4*>(g_agg1)[idx] = a;
    }
}

// ---------------- edge aggregation: agg[dst] += hs[src] --------------------
// 16 lanes per edge; one float4 load + one vector reduction per lane.
template <int LAYER>
__global__ void __launch_bounds__(256) k_edge(const int* __restrict__ src,
                                              const int* __restrict__ dst) {
    const float* hs = (LAYER == 0) ? g_hs1 : g_hs2;
    float* agg      = (LAYER == 0) ? g_agg1 : g_agg2;

    unsigned tid = blockIdx.x * blockDim.x + threadIdx.x;
    unsigned e = tid >> 4;
    unsigned c = tid & 15u;
    int s = __ldg(&src[e]);
    int d = __ldg(&dst[e]);
    float4 v = __ldg(reinterpret_cast<const float4*>(hs) + (size_t)s * 16 + c);
    red_add_v4(reinterpret_cast<float*>(
                   reinterpret_cast<float4*>(agg) + (size_t)d * 16 + c), v);
}

// ---------------- layer 2 node GEMM --------------------------------------
// t = tanh(dinv*agg1 + b1); hs2 = dinv * (t @ W2); agg2 init = hs2.
__global__ void __launch_bounds__(128) k_h2(const float* __restrict__ W2,
                                            const float* __restrict__ b1) {
    __shared__ float sW[H1 * H2];
    __shared__ float sb[H1];
    for (int i = threadIdx.x; i < H1 * H2; i += blockDim.x) sW[i] = W2[i];
    if (threadIdx.x < H1) sb[threadIdx.x] = b1[threadIdx.x];
    __syncthreads();

    int node = blockIdx.x * blockDim.x + threadIdx.x;
    float dinv = g_dinv[node];

    float t[H1];
#pragma unroll
    for (int h = 0; h < H1; h += 4) {
        float4 a = reinterpret_cast<const float4*>(g_agg1)[node * (H1 / 4) + (h >> 2)];
        t[h + 0] = tanhx(fmaf(a.x, dinv, sb[h + 0]));
        t[h + 1] = tanhx(fmaf(a.y, dinv, sb[h + 1]));
        t[h + 2] = tanhx(fmaf(a.z, dinv, sb[h + 2]));
        t[h + 3] = tanhx(fmaf(a.w, dinv, sb[h + 3]));
    }

#pragma unroll
    for (int j0 = 0; j0 < H2; j0 += 16) {
        float acc[16];
#pragma unroll
        for (int jj = 0; jj < 16; jj++) acc[jj] = 0.f;
#pragma unroll
        for (int h = 0; h < H1; h++) {
            float tv = t[h];
#pragma unroll
            for (int jj = 0; jj < 16; jj++)
                acc[jj] = fmaf(tv, sW[h * H2 + j0 + jj], acc[jj]);
        }
#pragma unroll
        for (int jj = 0; jj < 16; jj += 4) {
            float4 o = make_float4(acc[jj + 0] * dinv, acc[jj + 1] * dinv,
                                   acc[jj + 2] * dinv, acc[jj + 3] * dinv);
            int idx = node * (H2 / 4) + ((j0 + jj) >> 2);
            reinterpret_cast<float4*>(g_hs2)[idx] = o;
            reinterpret_cast<float4*>(g_agg2)[idx] = o;
        }
    }
}

// ---------------- output init + fused tanh/FC -----------------------------
__global__ void k_out_init(const float* __restrict__ bfc, float* __restrict__ out) {
    int i = blockIdx.x * blockDim.x + threadIdx.x;
    if (i < N_GRAPHS * OUT_F) out[i] = bfc[i % OUT_F];
}

#define FC_CHUNKS 64
#define FC_KC ((NPG * H2) / FC_CHUNKS)  // 2048 k-elements per chunk
#define FC_GPB 4                        // graphs per block (Wfc L1 reuse)

__global__ void __launch_bounds__(256) k_fc(const float* __restrict__ Wfc,
                                            const float* __restrict__ b2,
                                            float* __restrict__ out) {
    __shared__ float sred[8][OUT_F];
    int chunk = blockIdx.x & (FC_CHUNKS - 1);
    int ggrp  = blockIdx.x >> 6;  // 0..7
    int t = threadIdx.x;
    int lane = t & 31, warp = t >> 5;
    int kbase = chunk * FC_KC;

    for (int gg = 0; gg < FC_GPB; gg++) {
        int g = ggrp * FC_GPB + gg;
        float acc[OUT_F];
#pragma unroll
        for (int o = 0; o < OUT_F; o++) acc[o] = 0.f;

#pragma unroll
        for (int i = 0; i < FC_KC / 256; i++) {
            int k = kbase + i * 256 + t;            // [0, 131072)
            int n = g * NPG + (k >> 6);
            int h = k & 63;
            float v = tanhx(fmaf(__ldg(&g_agg2[(size_t)g * (NPG * H2) + k]),
                                 g_dinv[n], __ldg(&b2[h])));
            const float4* w4 = reinterpret_cast<const float4*>(Wfc + (size_t)k * OUT_F);
            float4 w0 = __ldg(&w4[0]);
            float4 w1 = __ldg(&w4[1]);
            float4 w2 = __ldg(&w4[2]);
            acc[0]  = fmaf(v, w0.x, acc[0]);
            acc[1]  = fmaf(v, w0.y, acc[1]);
            acc[2]  = fmaf(v, w0.z, acc[2]);
            acc[3]  = fmaf(v, w0.w, acc[3]);
            acc[4]  = fmaf(v, w1.x, acc[4]);
            acc[5]  = fmaf(v, w1.y, acc[5]);
            acc[6]  = fmaf(v, w1.z, acc[6]);
            acc[7]  = fmaf(v, w1.w, acc[7]);
            acc[8]  = fmaf(v, w2.x, acc[8]);
            acc[9]  = fmaf(v, w2.y, acc[9]);
            acc[10] = fmaf(v, w2.z, acc[10]);
            acc[11] = fmaf(v, w2.w, acc[11]);
        }

#pragma unroll
        for (int o = 0; o < OUT_F; o++) {
            float s = acc[o];
#pragma unroll
            for (int off = 16; off > 0; off >>= 1)
                s += __shfl_down_sync(0xffffffffu, s, off);
            if (lane == 0) sred[warp][o] = s;
        }
        __syncthreads();
        if (t < OUT_F) {
            float s = 0.f;
#pragma unroll
            for (int w = 0; w < 8; w++) s += sred[w][t];
            atomicAdd(&out[g * OUT_F + t], s);
        }
        __syncthreads();
    }
}

// ---------------- launcher -------------------------------------------------
extern "C" void kernel_launch(void* const* d_in, const int* in_sizes, int n_in,
                              void* d_out, int out_size) {
    (void)in_sizes; (void)n_in; (void)out_size;
    const float* x   = (const float*)d_in[0];
    const int*   ei  = (const int*)d_in[1];
    // d_in[2] = batch (unused: layout is a fixed reshape)
    const float* W1  = (const float*)d_in[3];
    const float* b1  = (const float*)d_in[4];
    const float* W2  = (const float*)d_in[5];
    const float* b2  = (const float*)d_in[6];
    const float* Wfc = (const float*)d_in[7];
    const float* bfc = (const float*)d_in[8];
    float* out = (float*)d_out;

    const int* src = ei;
    const int* dst = ei + N_EDGES;

    k_deg_init<<<N_NODES / 256, 256>>>();
    k_deg<<<N_EDGES / 256, 256>>>(dst);
    k_h1<<<N_NODES / 256, 256>>>(x, W1);
    k_edge<0><<<(N_EDGES * 16) / 256, 256>>>(src, dst);
    k_h2<<<N_NODES / 128, 128>>>(W2, b1);
    k_edge<1><<<(N_EDGES * 16) / 256, 256>>>(src, dst);
    k_out_init<<<2, 256>>>(bfc, out);
    k_fc<<<8 * FC_CHUNKS, 256>>>(Wfc, b2, out);
}